// round 4
// baseline (speedup 1.0000x reference)
#include <cuda_runtime.h>
#include <math.h>

// Chamfer distance, N=M=16384, D=3 — fused single-pass over the distance matrix.
// d^2(i,j) = sq_a[i] + (sq_b[j] - 2*a.b[j]).
// Each block computes a 1024x512 tile ONCE, producing both row-mins (registers)
// and col-mins (in-thread tree + 3-level shfl_xor + smem partials).
// Inner: 3 fma.rn.f32x2 + 1 add.rn.f32x2 per (query, j-pair) -> fma-pipe bound.

#define MAXN   16384
#define TPB    128
#define RQT    8
#define ICHUNK (TPB*RQT)   // 1024 rows per block
#define JCHUNK 512         // cols per block
#define JPAIRS (JCHUNK/2)  // 256 packed col-pairs (32B each -> 8KB smem)

typedef unsigned long long ull;

__device__ unsigned g_min1[MAXN];   // min d^2 per row (clamped >=0, ordered uint bits)
__device__ unsigned g_min2[MAXN];   // min d^2 per col

__device__ __forceinline__ ull dup2(float x) {
    unsigned u = __float_as_uint(x);
    return ((ull)u) | (((ull)u) << 32);
}
__device__ __forceinline__ ull fma2(ull a, ull b, ull c) {
    ull d;
    asm("fma.rn.f32x2 %0, %1, %2, %3;" : "=l"(d) : "l"(a), "l"(b), "l"(c));
    return d;
}
__device__ __forceinline__ ull add2(ull a, ull b) {
    ull d;
    asm("add.rn.f32x2 %0, %1, %2;" : "=l"(d) : "l"(a), "l"(b));
    return d;
}
__device__ __forceinline__ float lo32(ull v) { return __uint_as_float((unsigned)v); }
__device__ __forceinline__ float hi32(ull v) { return __uint_as_float((unsigned)(v >> 32)); }

__global__ void init_kernel(float* __restrict__ out) {
    int i = blockIdx.x * blockDim.x + threadIdx.x;
    if (i == 0) out[0] = 0.0f;
    if (i < MAXN) { g_min1[i] = 0x7F800000u; g_min2[i] = 0x7F800000u; }
}

__global__ void __launch_bounds__(TPB)
chamfer_fused(const float* __restrict__ p1, int n1,
              const float* __restrict__ p2, int n2) {
    __shared__ float4 tile[JPAIRS * 2];          // 8 KB packed (-2b, sq_b)
    __shared__ float2 cpart[4][JPAIRS][4];       // 32 KB col-min partials {lo,hi}

    const float INF = __uint_as_float(0x7F800000u);
    int jbase = blockIdx.y * JCHUNK;

    // Build packed db tile in-block from raw p2 (pair layout:
    // tile[2p]=(-2x0,-2x1,-2y0,-2y1), tile[2p+1]=(-2z0,-2z1,sq0,sq1))
    #pragma unroll
    for (int k = 0; k < JPAIRS / TPB; k++) {
        int pk = k * TPB + threadIdx.x;
        int j0 = jbase + 2 * pk, j1 = j0 + 1;
        float x0=0.f,y0=0.f,z0=0.f,s0=INF, x1=0.f,y1=0.f,z1=0.f,s1=INF;
        if (j0 < n2) { x0=p2[3*j0]; y0=p2[3*j0+1]; z0=p2[3*j0+2]; s0=x0*x0+y0*y0+z0*z0; }
        if (j1 < n2) { x1=p2[3*j1]; y1=p2[3*j1+1]; z1=p2[3*j1+2]; s1=x1*x1+y1*y1+z1*z1; }
        tile[2*pk]   = make_float4(-2.f*x0, -2.f*x1, -2.f*y0, -2.f*y1);
        tile[2*pk+1] = make_float4(-2.f*z0, -2.f*z1, s0, s1);
    }

    // Load RQT query rows per thread
    int ibase = blockIdx.x * ICHUNK + threadIdx.x;
    ull  axx[RQT], ayy[RQT], azz[RQT], sq2[RQT];
    bool valid[RQT];
    #pragma unroll
    for (int r = 0; r < RQT; r++) {
        int i = ibase + r * TPB;
        float x = 0.f, y = 0.f, z = 0.f, sq = INF;  // invalid rows: s=INF, never win col-min
        valid[r] = (i < n1);
        if (valid[r]) { x = p1[3*i]; y = p1[3*i+1]; z = p1[3*i+2]; sq = x*x+y*y+z*z; }
        axx[r] = dup2(x); ayy[r] = dup2(y); azz[r] = dup2(z); sq2[r] = dup2(sq);
    }
    __syncthreads();

    float m0[RQT], m1[RQT];
    #pragma unroll
    for (int r = 0; r < RQT; r++) { m0[r] = INF; m1[r] = INF; }

    int lane = threadIdx.x & 31, w = threadIdx.x >> 5;
    const ulonglong2* t2 = (const ulonglong2*)tile;

    #pragma unroll 2
    for (int p = 0; p < JPAIRS; p++) {
        ulonglong2 v0 = t2[2*p];       // (bx0,bx1) (by0,by1)
        ulonglong2 v1 = t2[2*p + 1];   // (bz0,bz1) (sq0,sq1)
        float clo, chi;
        #pragma unroll
        for (int r = 0; r < RQT; r++) {
            ull t = fma2(axx[r], v0.x, fma2(ayy[r], v0.y, fma2(azz[r], v1.x, v1.y)));
            ull s = add2(t, sq2[r]);          // s = full d^2 (pair)
            float slo = lo32(s), shi = hi32(s);
            m0[r] = fminf(m0[r], slo);
            m1[r] = fminf(m1[r], shi);
            if (r == 0) { clo = slo; chi = shi; }
            else        { clo = fminf(clo, slo); chi = fminf(chi, shi); }
        }
        // 3-level butterfly: lanes 0..3 end with disjoint 8-lane group mins
        clo = fminf(clo, __shfl_xor_sync(0xffffffffu, clo, 16));
        chi = fminf(chi, __shfl_xor_sync(0xffffffffu, chi, 16));
        clo = fminf(clo, __shfl_xor_sync(0xffffffffu, clo, 8));
        chi = fminf(chi, __shfl_xor_sync(0xffffffffu, chi, 8));
        clo = fminf(clo, __shfl_xor_sync(0xffffffffu, clo, 4));
        chi = fminf(chi, __shfl_xor_sync(0xffffffffu, chi, 4));
        if (lane < 4) cpart[w][p][lane] = make_float2(clo, chi);
    }

    // Row mins -> global
    #pragma unroll
    for (int r = 0; r < RQT; r++) {
        if (!valid[r]) continue;
        float d2 = fmaxf(fminf(m0[r], m1[r]), 0.0f);
        atomicMin(&g_min1[ibase + r * TPB], __float_as_uint(d2));
    }

    __syncthreads();

    // Col mins: reduce 16 partials per column, then global atomic
    for (int jj = threadIdx.x; jj < JCHUNK; jj += TPB) {
        int p = jj >> 1, h = jj & 1;
        float v = INF;
        #pragma unroll
        for (int ww = 0; ww < 4; ww++) {
            #pragma unroll
            for (int l = 0; l < 4; l++) {
                float2 c = cpart[ww][p][l];
                v = fminf(v, h ? c.y : c.x);
            }
        }
        int jg = jbase + jj;
        if (jg < n2) {
            float d2 = fmaxf(v, 0.0f);
            atomicMin(&g_min2[jg], __float_as_uint(d2));
        }
    }
}

__global__ void chamfer_reduce(float* __restrict__ out, int n1, int n2) {
    __shared__ float ssum[32];
    int i = blockIdx.x * blockDim.x + threadIdx.x;
    float d = 0.0f;
    if (i < n1) {
        d = sqrtf(__uint_as_float(g_min1[i]));
    } else {
        int j = i - n1;
        if (j < n2) d = sqrtf(__uint_as_float(g_min2[j]));
    }
    #pragma unroll
    for (int o = 16; o; o >>= 1) d += __shfl_down_sync(0xffffffffu, d, o);
    int lane = threadIdx.x & 31, w = threadIdx.x >> 5;
    if (lane == 0) ssum[w] = d;
    __syncthreads();
    if (w == 0) {
        float v = (lane < (int)(blockDim.x >> 5)) ? ssum[lane] : 0.0f;
        #pragma unroll
        for (int o = 16; o; o >>= 1) v += __shfl_down_sync(0xffffffffu, v, o);
        if (lane == 0) atomicAdd(out, v);
    }
}

extern "C" void kernel_launch(void* const* d_in, const int* in_sizes, int n_in,
                              void* d_out, int out_size) {
    const float* p1 = (const float*)d_in[0];
    const float* p2 = (const float*)d_in[1];
    int n1 = in_sizes[0] / 3;
    int n2 = in_sizes[1] / 3;
    float* out = (float*)d_out;

    init_kernel<<<(MAXN + 255) / 256, 256>>>(out);

    int iblocks = (n1 + ICHUNK - 1) / ICHUNK;   // 16
    int jsplits = (n2 + JCHUNK - 1) / JCHUNK;   // 32
    dim3 grid(iblocks, jsplits);                // 512 blocks
    chamfer_fused<<<grid, TPB>>>(p1, n1, p2, n2);

    int total = n1 + n2;
    chamfer_reduce<<<(total + 511) / 512, 512>>>(out, n1, n2);
}

// round 5
// speedup vs baseline: 1.2274x; 1.2274x over previous
#include <cuda_runtime.h>
#include <math.h>

// Chamfer, N=M=16384, D=3. Single fused pass; lanes own columns.
// Block = 256 rows x 1024 cols. Per thread: 4 column-pairs in registers.
// t' = sq_b - 2 a.b (3 FFMA2, sq_b folded as fma c-input).
// Row-min: min t' (in-thread over 8 cols, then 5-level shfl per row), +sq_a at end.
// Col-min: s = t' + sq_a (1 ADD2), register accumulators, stored once per block.
// No atomics, no init kernel: partial-min slots + one reduce kernel.

#define TPB     128
#define RCH     256            // rows per block
#define CPT     4              // colpairs per thread
#define JCH     (TPB*CPT*2)    // 1024 cols per block
#define IBLK    64             // 16384 / RCH
#define JBLK    16             // 16384 / JCH
#define MAXN    16384

typedef unsigned long long ull;

__device__ float    g_rmin[JBLK][MAXN];   // per-jsplit row-min partial (d^2, clamped)
__device__ float    g_cmin[IBLK][MAXN];   // per-isplit col-min partial
__device__ float    g_bsum[64];
__device__ unsigned g_ctr = 0;

__device__ __forceinline__ ull pack2(float a, float b) {
    return ((ull)__float_as_uint(a)) | (((ull)__float_as_uint(b)) << 32);
}
__device__ __forceinline__ ull dup2(float x) { return pack2(x, x); }
__device__ __forceinline__ ull fma2(ull a, ull b, ull c) {
    ull d;
    asm("fma.rn.f32x2 %0, %1, %2, %3;" : "=l"(d) : "l"(a), "l"(b), "l"(c));
    return d;
}
__device__ __forceinline__ ull add2(ull a, ull b) {
    ull d;
    asm("add.rn.f32x2 %0, %1, %2;" : "=l"(d) : "l"(a), "l"(b));
    return d;
}
__device__ __forceinline__ float lo32(ull v) { return __uint_as_float((unsigned)v); }
__device__ __forceinline__ float hi32(ull v) { return __uint_as_float((unsigned)(v >> 32)); }

__global__ void __launch_bounds__(TPB)
chamfer_fused(const float* __restrict__ p1, int n1,
              const float* __restrict__ p2, int n2) {
    __shared__ ulonglong2 qxy[RCH];        // {(x,x),(y,y)}   4 KB
    __shared__ ulonglong2 qzs[RCH];        // {(z,z),(sq,sq)} 4 KB
    __shared__ float rowpart[4][RCH];      // per-warp row partial mins (t')  4 KB

    const float INF = __uint_as_float(0x7F800000u);
    const int tid  = threadIdx.x;
    const int lane = tid & 31, w = tid >> 5;
    const int rbase = blockIdx.x * RCH;
    const int jbase = blockIdx.y * JCH;

    // Stage query rows into smem as duplicated pairs
    #pragma unroll
    for (int k = 0; k < RCH / TPB; k++) {
        int rr = k * TPB + tid;
        int i  = rbase + rr;
        float x = 0.f, y = 0.f, z = 0.f, sq = INF;
        if (i < n1) { x = p1[3*i]; y = p1[3*i+1]; z = p1[3*i+2]; sq = x*x + y*y + z*z; }
        qxy[rr] = make_ulonglong2(dup2(x), dup2(y));
        qzs[rr] = make_ulonglong2(dup2(z), dup2(sq));
    }

    // Load this thread's 4 column-pairs (8 db points) into registers
    ull bxx[CPT], byy[CPT], bzz[CPT], bsq[CPT];
    #pragma unroll
    for (int c = 0; c < CPT; c++) {
        int cp = tid + c * TPB;            // local colpair 0..511
        int j0 = jbase + 2 * cp, j1 = j0 + 1;
        float x0=0.f,y0=0.f,z0=0.f,s0=INF, x1=0.f,y1=0.f,z1=0.f,s1=INF;
        if (j0 < n2) { x0=p2[3*j0]; y0=p2[3*j0+1]; z0=p2[3*j0+2]; s0=x0*x0+y0*y0+z0*z0; }
        if (j1 < n2) { x1=p2[3*j1]; y1=p2[3*j1+1]; z1=p2[3*j1+2]; s1=x1*x1+y1*y1+z1*z1; }
        bxx[c] = pack2(-2.f*x0, -2.f*x1);
        byy[c] = pack2(-2.f*y0, -2.f*y1);
        bzz[c] = pack2(-2.f*z0, -2.f*z1);
        bsq[c] = pack2(s0, s1);
    }
    __syncthreads();

    float cm0[CPT], cm1[CPT];
    #pragma unroll
    for (int c = 0; c < CPT; c++) { cm0[c] = INF; cm1[c] = INF; }

    #pragma unroll 4
    for (int ii = 0; ii < RCH; ii++) {
        ulonglong2 axy = qxy[ii];
        ulonglong2 azs = qzs[ii];
        float rp;
        #pragma unroll
        for (int c = 0; c < CPT; c++) {
            ull t = fma2(bxx[c], axy.x, fma2(byy[c], axy.y, fma2(bzz[c], azs.x, bsq[c])));
            ull s = add2(t, azs.y);                 // full d^2 for the col path
            cm0[c] = fminf(cm0[c], lo32(s));
            cm1[c] = fminf(cm1[c], hi32(s));
            float u = fminf(lo32(t), hi32(t));      // row path on t' (sq_a deferred)
            rp = (c == 0) ? u : fminf(rp, u);
        }
        rp = fminf(rp, __shfl_xor_sync(0xffffffffu, rp, 16));
        rp = fminf(rp, __shfl_xor_sync(0xffffffffu, rp, 8));
        rp = fminf(rp, __shfl_xor_sync(0xffffffffu, rp, 4));
        rp = fminf(rp, __shfl_xor_sync(0xffffffffu, rp, 2));
        rp = fminf(rp, __shfl_xor_sync(0xffffffffu, rp, 1));
        if (lane == 0) rowpart[w][ii] = rp;
    }
    __syncthreads();

    // Row partials: min over 4 warps, add sq_a, clamp, store slot
    #pragma unroll
    for (int k = 0; k < RCH / TPB; k++) {
        int rr = k * TPB + tid;
        float v = fminf(fminf(rowpart[0][rr], rowpart[1][rr]),
                        fminf(rowpart[2][rr], rowpart[3][rr]));
        float sq = lo32(qzs[rr].y);
        g_rmin[blockIdx.y][rbase + rr] = fmaxf(v + sq, 0.0f);
    }

    // Col partials: clamp, store slot (float2 per pair, coalesced)
    #pragma unroll
    for (int c = 0; c < CPT; c++) {
        int cp = tid + c * TPB;
        float2 v = make_float2(fmaxf(cm0[c], 0.0f), fmaxf(cm1[c], 0.0f));
        *(float2*)&g_cmin[blockIdx.x][jbase + 2 * cp] = v;
    }
}

#define RTPB 512
#define RGRID 64
__global__ void __launch_bounds__(RTPB)
chamfer_reduce(float* __restrict__ out, int n1, int n2) {
    __shared__ float ssum[RTPB / 32];
    const float INF = __uint_as_float(0x7F800000u);
    int gid = blockIdx.x * RTPB + threadIdx.x;

    float d = 0.0f;
    if (gid < MAXN) {                  // rows
        int r = gid;
        if (r < n1) {
            float v = INF;
            #pragma unroll
            for (int k = 0; k < JBLK; k++) v = fminf(v, g_rmin[k][r]);
            d = sqrtf(v);
        }
    } else {                           // cols
        int j = gid - MAXN;
        if (j < n2) {
            float v = INF;
            #pragma unroll
            for (int k = 0; k < IBLK; k++) v = fminf(v, g_cmin[k][j]);
            d = sqrtf(v);
        }
    }

    #pragma unroll
    for (int o = 16; o; o >>= 1) d += __shfl_down_sync(0xffffffffu, d, o);
    int lane = threadIdx.x & 31, w = threadIdx.x >> 5;
    if (lane == 0) ssum[w] = d;
    __syncthreads();
    if (w == 0) {
        float v = (lane < RTPB / 32) ? ssum[lane] : 0.0f;
        #pragma unroll
        for (int o = 16; o; o >>= 1) v += __shfl_down_sync(0xffffffffu, v, o);
        if (lane == 0) {
            g_bsum[blockIdx.x] = v;
            __threadfence();
            unsigned t = atomicAdd(&g_ctr, 1u);
            ssum[0] = __uint_as_float(t);
        }
    }
    __syncthreads();
    if (__float_as_uint(ssum[0]) == RGRID - 1) {   // last block finalizes
        if (w == 0) {
            float v = (lane < 32) ? ((lane < RGRID) ? g_bsum[lane] : 0.0f) : 0.0f;
            float v2 = (lane + 32 < RGRID) ? g_bsum[lane + 32] : 0.0f;
            v += v2;
            #pragma unroll
            for (int o = 16; o; o >>= 1) v += __shfl_down_sync(0xffffffffu, v, o);
            if (lane == 0) { out[0] = v; g_ctr = 0; }
        }
    }
}

extern "C" void kernel_launch(void* const* d_in, const int* in_sizes, int n_in,
                              void* d_out, int out_size) {
    const float* p1 = (const float*)d_in[0];
    const float* p2 = (const float*)d_in[1];
    int n1 = in_sizes[0] / 3;
    int n2 = in_sizes[1] / 3;
    float* out = (float*)d_out;

    dim3 grid(IBLK, JBLK);             // 64 x 16 = 1024 blocks
    chamfer_fused<<<grid, TPB>>>(p1, n1, p2, n2);
    chamfer_reduce<<<RGRID, RTPB>>>(out, n1, n2);
}

// round 6
// speedup vs baseline: 1.3655x; 1.1125x over previous
#include <cuda_runtime.h>
#include <math.h>

// Chamfer, N=M=16384, D=3. Fused single pass; lanes own columns.
// Block = 256 rows x 1024 cols; thread owns 4 col-pairs in registers.
// Inner row-iter: 3 FFMA2 + 1 ADD2 per colpair + 15 FMNMX + 1 STS  (issue 36 < fma 44).
// Row partials reduced from smem in a separate tiny phase per 32-row chunk.

#define TPB   128
#define RCH   256              // rows per block
#define CHRW  32               // rows per chunk (phase granularity)
#define NCHK  (RCH/CHRW)       // 8
#define CPT   4                // colpairs per thread
#define JCH   (TPB*CPT*2)      // 1024 cols per block
#define IBLK  64               // 16384/RCH
#define JBLK  16               // 16384/JCH
#define MAXN  16384
#define UPAD  132              // padded row stride for ubuf

typedef unsigned long long ull;

__device__ float    g_rmin[JBLK][MAXN];   // per-jsplit row-min partials (d^2, clamped)
__device__ float    g_cmin[IBLK][MAXN];   // per-isplit col-min partials
__device__ float    g_bsum[128];
__device__ unsigned g_ctr = 0;

__device__ __forceinline__ ull pack2(float a, float b) {
    return ((ull)__float_as_uint(a)) | (((ull)__float_as_uint(b)) << 32);
}
__device__ __forceinline__ ull dup2(float x) { return pack2(x, x); }
__device__ __forceinline__ ull fma2(ull a, ull b, ull c) {
    ull d;
    asm("fma.rn.f32x2 %0, %1, %2, %3;" : "=l"(d) : "l"(a), "l"(b), "l"(c));
    return d;
}
__device__ __forceinline__ ull add2(ull a, ull b) {
    ull d;
    asm("add.rn.f32x2 %0, %1, %2;" : "=l"(d) : "l"(a), "l"(b));
    return d;
}
__device__ __forceinline__ float lo32(ull v) { return __uint_as_float((unsigned)v); }
__device__ __forceinline__ float hi32(ull v) { return __uint_as_float((unsigned)(v >> 32)); }

__global__ void __launch_bounds__(TPB)
chamfer_fused(const float* __restrict__ p1, int n1,
              const float* __restrict__ p2, int n2) {
    __shared__ ulonglong2 qxy[RCH];          // {(x,x),(y,y)}   4 KB
    __shared__ ulonglong2 qzs[RCH];          // {(z,z),(sq,sq)} 4 KB
    __shared__ float ubuf[CHRW][UPAD];       // 16.5 KB row partials

    const float INF = __uint_as_float(0x7F800000u);
    const int tid  = threadIdx.x;
    const int lane = tid & 31, w = tid >> 5;
    const int rbase = blockIdx.x * RCH;
    const int jbase = blockIdx.y * JCH;

    // Stage query rows
    #pragma unroll
    for (int k = 0; k < RCH / TPB; k++) {
        int rr = k * TPB + tid;
        int i  = rbase + rr;
        float x = 0.f, y = 0.f, z = 0.f, sq = INF;   // invalid rows never win col-min
        if (i < n1) { x = p1[3*i]; y = p1[3*i+1]; z = p1[3*i+2]; sq = x*x + y*y + z*z; }
        qxy[rr] = make_ulonglong2(dup2(x), dup2(y));
        qzs[rr] = make_ulonglong2(dup2(z), dup2(sq));
    }

    // This thread's 4 column-pairs in registers
    ull bxx[CPT], byy[CPT], bzz[CPT], bsq[CPT];
    #pragma unroll
    for (int c = 0; c < CPT; c++) {
        int cp = tid + c * TPB;
        int j0 = jbase + 2 * cp, j1 = j0 + 1;
        float x0=0.f,y0=0.f,z0=0.f,s0=INF, x1=0.f,y1=0.f,z1=0.f,s1=INF;
        if (j0 < n2) { x0=p2[3*j0]; y0=p2[3*j0+1]; z0=p2[3*j0+2]; s0=x0*x0+y0*y0+z0*z0; }
        if (j1 < n2) { x1=p2[3*j1]; y1=p2[3*j1+1]; z1=p2[3*j1+2]; s1=x1*x1+y1*y1+z1*z1; }
        bxx[c] = pack2(-2.f*x0, -2.f*x1);
        byy[c] = pack2(-2.f*y0, -2.f*y1);
        bzz[c] = pack2(-2.f*z0, -2.f*z1);
        bsq[c] = pack2(s0, s1);
    }
    __syncthreads();

    float cm0[CPT], cm1[CPT];
    #pragma unroll
    for (int c = 0; c < CPT; c++) { cm0[c] = INF; cm1[c] = INF; }

    #pragma unroll 1
    for (int chunk = 0; chunk < NCHK; chunk++) {
        const int r0 = chunk * CHRW;

        // Phase 1: compute; row partial u -> 1 STS (no shuffles in hot loop)
        #pragma unroll 4
        for (int rr = 0; rr < CHRW; rr++) {
            ulonglong2 axy = qxy[r0 + rr];
            ulonglong2 azs = qzs[r0 + rr];
            float u;
            #pragma unroll
            for (int c = 0; c < CPT; c++) {
                ull t = fma2(bxx[c], axy.x, fma2(byy[c], axy.y, fma2(bzz[c], azs.x, bsq[c])));
                ull s = add2(t, azs.y);              // full d^2 (col path)
                cm0[c] = fminf(cm0[c], lo32(s));
                cm1[c] = fminf(cm1[c], hi32(s));
                float uc = fminf(lo32(t), hi32(t));  // row path on t' (sq_a deferred)
                u = (c == 0) ? uc : fminf(u, uc);
            }
            ubuf[rr][tid] = u;
        }
        __syncthreads();

        // Phase 2: reduce 128 partials per row (4 lanes/row, vec4 + 2 shfl)
        {
            int row = (w << 3) + (lane >> 2);        // 0..31
            int q   = lane & 3;
            const float4* src = (const float4*)&ubuf[row][q * 32];
            float4 v4 = src[0];
            #pragma unroll
            for (int k = 1; k < 8; k++) {
                float4 t4 = src[k];
                v4.x = fminf(v4.x, t4.x); v4.y = fminf(v4.y, t4.y);
                v4.z = fminf(v4.z, t4.z); v4.w = fminf(v4.w, t4.w);
            }
            float v = fminf(fminf(v4.x, v4.y), fminf(v4.z, v4.w));
            v = fminf(v, __shfl_xor_sync(0xffffffffu, v, 1));
            v = fminf(v, __shfl_xor_sync(0xffffffffu, v, 2));
            if (q == 0) {
                int rglob = rbase + r0 + row;
                if (rglob < n1) {
                    float sq = lo32(qzs[r0 + row].y);
                    g_rmin[blockIdx.y][rglob] = fmaxf(v + sq, 0.0f);
                }
            }
        }
        __syncthreads();
    }

    // Col partials: clamp, store (float2 per pair, coalesced)
    #pragma unroll
    for (int c = 0; c < CPT; c++) {
        int cp = tid + c * TPB;
        float2 v = make_float2(fmaxf(cm0[c], 0.0f), fmaxf(cm1[c], 0.0f));
        *(float2*)&g_cmin[blockIdx.x][jbase + 2 * cp] = v;
    }
}

#define RTPB  256
#define RGRID 128
__global__ void __launch_bounds__(RTPB)
chamfer_reduce(float* __restrict__ out, int n1, int n2) {
    __shared__ float ssum[RTPB / 32];
    const float INF = __uint_as_float(0x7F800000u);
    int gid = blockIdx.x * RTPB + threadIdx.x;

    float d = 0.0f;
    if (gid < MAXN) {                  // rows
        int r = gid;
        if (r < n1) {
            float v = INF;
            #pragma unroll
            for (int k = 0; k < JBLK; k++) v = fminf(v, g_rmin[k][r]);
            d = sqrtf(v);
        }
    } else {                           // cols
        int j = gid - MAXN;
        if (j < n2) {
            float v = INF;
            #pragma unroll
            for (int k = 0; k < IBLK; k++) v = fminf(v, g_cmin[k][j]);
            d = sqrtf(v);
        }
    }

    #pragma unroll
    for (int o = 16; o; o >>= 1) d += __shfl_down_sync(0xffffffffu, d, o);
    int lane = threadIdx.x & 31, w = threadIdx.x >> 5;
    if (lane == 0) ssum[w] = d;
    __syncthreads();
    if (w == 0) {
        float v = (lane < RTPB / 32) ? ssum[lane] : 0.0f;
        #pragma unroll
        for (int o = 16; o; o >>= 1) v += __shfl_down_sync(0xffffffffu, v, o);
        if (lane == 0) {
            g_bsum[blockIdx.x] = v;
            __threadfence();
            unsigned t = atomicAdd(&g_ctr, 1u);
            ssum[0] = __uint_as_float(t);
        }
    }
    __syncthreads();
    if (__float_as_uint(ssum[0]) == RGRID - 1) {   // last block finalizes
        __threadfence();
        if (w == 0) {
            float v = 0.0f;
            #pragma unroll
            for (int k = 0; k < RGRID / 32; k++) v += g_bsum[k * 32 + lane];
            #pragma unroll
            for (int o = 16; o; o >>= 1) v += __shfl_down_sync(0xffffffffu, v, o);
            if (lane == 0) { out[0] = v; g_ctr = 0; }
        }
    }
}

extern "C" void kernel_launch(void* const* d_in, const int* in_sizes, int n_in,
                              void* d_out, int out_size) {
    const float* p1 = (const float*)d_in[0];
    const float* p2 = (const float*)d_in[1];
    int n1 = in_sizes[0] / 3;
    int n2 = in_sizes[1] / 3;
    float* out = (float*)d_out;

    dim3 grid(IBLK, JBLK);             // 64 x 16 = 1024 blocks
    chamfer_fused<<<grid, TPB>>>(p1, n1, p2, n2);
    chamfer_reduce<<<RGRID, RTPB>>>(out, n1, n2);
}

// round 7
// speedup vs baseline: 1.3661x; 1.0004x over previous
#include <cuda_runtime.h>
#include <math.h>

// Chamfer, N=M=16384, D=3. Fused single pass; lanes own columns.
// Block = 256 rows x 1024 cols; thread owns 4 col-pairs in registers.
// Row/col mins -> global atomicMin on clamped-f32 bits; tiny finalize kernel.
// 4 launches/call so ncu (-s 5 -c 1) captures the FUSED kernel (5 mod 4 == 1).

#define TPB   128
#define RCH   256              // rows per block
#define CHRW  32               // rows per chunk
#define NCHK  (RCH/CHRW)       // 8
#define CPT   4                // colpairs per thread
#define JCH   (TPB*CPT*2)      // 1024 cols per block
#define IBLK  64               // 16384/RCH
#define JBLK  16               // 16384/JCH
#define MAXN  16384
#define UPAD  132

typedef unsigned long long ull;

__device__ unsigned g_rmin2[MAXN];   // min d^2 per row (clamped>=0, uint-ordered)
__device__ unsigned g_cmin2[MAXN];   // min d^2 per col

__device__ __forceinline__ ull pack2(float a, float b) {
    return ((ull)__float_as_uint(a)) | (((ull)__float_as_uint(b)) << 32);
}
__device__ __forceinline__ ull dup2(float x) { return pack2(x, x); }
__device__ __forceinline__ ull fma2(ull a, ull b, ull c) {
    ull d;
    asm("fma.rn.f32x2 %0, %1, %2, %3;" : "=l"(d) : "l"(a), "l"(b), "l"(c));
    return d;
}
__device__ __forceinline__ ull add2(ull a, ull b) {
    ull d;
    asm("add.rn.f32x2 %0, %1, %2;" : "=l"(d) : "l"(a), "l"(b));
    return d;
}
__device__ __forceinline__ float lo32(ull v) { return __uint_as_float((unsigned)v); }
__device__ __forceinline__ float hi32(ull v) { return __uint_as_float((unsigned)(v >> 32)); }

__global__ void init_kernel(float* __restrict__ out) {
    int i = blockIdx.x * blockDim.x + threadIdx.x;
    if (i == 0) out[0] = 0.0f;
    if (i < MAXN) { g_rmin2[i] = 0x7F800000u; g_cmin2[i] = 0x7F800000u; }
}

__global__ void __launch_bounds__(TPB)
chamfer_fused(const float* __restrict__ p1, int n1,
              const float* __restrict__ p2, int n2) {
    __shared__ ulonglong2 qxy[RCH];          // {(x,x),(y,y)}   4 KB
    __shared__ ulonglong2 qzs[RCH];          // {(z,z),(sq,sq)} 4 KB
    __shared__ float ubuf[CHRW][UPAD];       // 16.5 KB row partials

    const float INF = __uint_as_float(0x7F800000u);
    const int tid  = threadIdx.x;
    const int lane = tid & 31, w = tid >> 5;
    const int rbase = blockIdx.x * RCH;
    const int jbase = blockIdx.y * JCH;

    #pragma unroll
    for (int k = 0; k < RCH / TPB; k++) {
        int rr = k * TPB + tid;
        int i  = rbase + rr;
        float x = 0.f, y = 0.f, z = 0.f, sq = INF;   // invalid rows never win col-min
        if (i < n1) { x = p1[3*i]; y = p1[3*i+1]; z = p1[3*i+2]; sq = x*x + y*y + z*z; }
        qxy[rr] = make_ulonglong2(dup2(x), dup2(y));
        qzs[rr] = make_ulonglong2(dup2(z), dup2(sq));
    }

    ull bxx[CPT], byy[CPT], bzz[CPT], bsq[CPT];
    #pragma unroll
    for (int c = 0; c < CPT; c++) {
        int cp = tid + c * TPB;
        int j0 = jbase + 2 * cp, j1 = j0 + 1;
        float x0=0.f,y0=0.f,z0=0.f,s0=INF, x1=0.f,y1=0.f,z1=0.f,s1=INF;
        if (j0 < n2) { x0=p2[3*j0]; y0=p2[3*j0+1]; z0=p2[3*j0+2]; s0=x0*x0+y0*y0+z0*z0; }
        if (j1 < n2) { x1=p2[3*j1]; y1=p2[3*j1+1]; z1=p2[3*j1+2]; s1=x1*x1+y1*y1+z1*z1; }
        bxx[c] = pack2(-2.f*x0, -2.f*x1);
        byy[c] = pack2(-2.f*y0, -2.f*y1);
        bzz[c] = pack2(-2.f*z0, -2.f*z1);
        bsq[c] = pack2(s0, s1);
    }
    __syncthreads();

    float cm0[CPT], cm1[CPT];
    #pragma unroll
    for (int c = 0; c < CPT; c++) { cm0[c] = INF; cm1[c] = INF; }

    #pragma unroll 1
    for (int chunk = 0; chunk < NCHK; chunk++) {
        const int r0 = chunk * CHRW;

        // Phase 1: compute; row partial -> 1 STS (no shuffles in hot loop)
        #pragma unroll 4
        for (int rr = 0; rr < CHRW; rr++) {
            ulonglong2 axy = qxy[r0 + rr];
            ulonglong2 azs = qzs[r0 + rr];
            float uc[CPT];
            #pragma unroll
            for (int c = 0; c < CPT; c++) {
                ull t = fma2(bxx[c], axy.x, fma2(byy[c], axy.y, fma2(bzz[c], azs.x, bsq[c])));
                ull s = add2(t, azs.y);              // full d^2 (col path)
                cm0[c] = fminf(cm0[c], lo32(s));
                cm1[c] = fminf(cm1[c], hi32(s));
                uc[c] = fminf(lo32(t), hi32(t));     // row path on t' (sq_a deferred)
            }
            ubuf[rr][tid] = fminf(fminf(uc[0], uc[1]), fminf(uc[2], uc[3]));
        }
        __syncthreads();

        // Phase 2: reduce 128 partials per row (4 lanes/row, vec4 + 2 shfl)
        {
            int row = (w << 3) + (lane >> 2);
            int q   = lane & 3;
            const float4* src = (const float4*)&ubuf[row][q * 32];
            float4 v4 = src[0];
            #pragma unroll
            for (int k = 1; k < 8; k++) {
                float4 t4 = src[k];
                v4.x = fminf(v4.x, t4.x); v4.y = fminf(v4.y, t4.y);
                v4.z = fminf(v4.z, t4.z); v4.w = fminf(v4.w, t4.w);
            }
            float v = fminf(fminf(v4.x, v4.y), fminf(v4.z, v4.w));
            v = fminf(v, __shfl_xor_sync(0xffffffffu, v, 1));
            v = fminf(v, __shfl_xor_sync(0xffffffffu, v, 2));
            if (q == 0) {
                int rglob = rbase + r0 + row;
                if (rglob < n1) {
                    float sq = lo32(qzs[r0 + row].y);
                    float d2 = fmaxf(v + sq, 0.0f);
                    atomicMin(&g_rmin2[rglob], __float_as_uint(d2));
                }
            }
        }
        __syncthreads();
    }

    // Col partials -> global atomicMin
    #pragma unroll
    for (int c = 0; c < CPT; c++) {
        int cp = tid + c * TPB;
        int j0 = jbase + 2 * cp;
        if (j0 < n2)     atomicMin(&g_cmin2[j0],     __float_as_uint(fmaxf(cm0[c], 0.0f)));
        if (j0 + 1 < n2) atomicMin(&g_cmin2[j0 + 1], __float_as_uint(fmaxf(cm1[c], 0.0f)));
    }
}

#define FTPB 512
__global__ void __launch_bounds__(FTPB)
chamfer_finalize(float* __restrict__ out, int n1, int n2) {
    __shared__ float ssum[FTPB / 32];
    int gid = blockIdx.x * FTPB + threadIdx.x;
    float d = 0.0f;
    if (gid < MAXN) {
        if (gid < n1) d = sqrtf(__uint_as_float(g_rmin2[gid]));
    } else {
        int j = gid - MAXN;
        if (j < n2) d = sqrtf(__uint_as_float(g_cmin2[j]));
    }
    #pragma unroll
    for (int o = 16; o; o >>= 1) d += __shfl_down_sync(0xffffffffu, d, o);
    int lane = threadIdx.x & 31, w = threadIdx.x >> 5;
    if (lane == 0) ssum[w] = d;
    __syncthreads();
    if (w == 0) {
        float v = (lane < FTPB / 32) ? ssum[lane] : 0.0f;
        #pragma unroll
        for (int o = 16; o; o >>= 1) v += __shfl_down_sync(0xffffffffu, v, o);
        if (lane == 0) atomicAdd(out, v);
    }
}

__global__ void dummy_pad() {}   // pads launch count to 4 so ncu -s 5 hits the fused kernel

extern "C" void kernel_launch(void* const* d_in, const int* in_sizes, int n_in,
                              void* d_out, int out_size) {
    const float* p1 = (const float*)d_in[0];
    const float* p2 = (const float*)d_in[1];
    int n1 = in_sizes[0] / 3;
    int n2 = in_sizes[1] / 3;
    float* out = (float*)d_out;

    init_kernel<<<(MAXN + 511) / 512, 512>>>(out);
    dim3 grid(IBLK, JBLK);             // 64 x 16 = 1024 blocks
    chamfer_fused<<<grid, TPB>>>(p1, n1, p2, n2);
    chamfer_finalize<<<(2 * MAXN + FTPB - 1) / FTPB, FTPB>>>(out, n1, n2);
    dummy_pad<<<1, 32>>>();
}